// round 12
// baseline (speedup 1.0000x reference)
#include <cuda_runtime.h>
#include <cstdint>
#include <math.h>

typedef unsigned long long ull;

#define BB 128
#define SS 2048
#define QQ 1000
#define KK 5
#define MM 50
#define DK 64
#define DV 128
#define SG 32            // scan staging group size

// ---------------- device scratch / tables ----------------
__device__ float g_attn[QQ * 52];          // softmax(q_e @ key^T), row padded to 52 (cols 50,51 = 0)
__device__ float4 g_ea[QQ * KK * DV];      // per (q,r,v): (-erase, -erase, add, add)
__device__ float g_qsum[QQ * 64];          // q_e @ summary_w[128:] + summary_b, j padded to 64
__device__ float g_alpha[QQ];
__device__ float g_beta[QQ * 4];
__device__ ull   g_wt2[DV * 32];           // summary_w[:128] packed float2 over j-pairs
__device__ float g_thw[64];                // theta_w padded to 64 with zeros
__device__ float g_readp[2 * BB * SS * DV];  // 268MB partial read scratch [h][b][s][v]

// ---------------- f32x2 helpers ----------------
__device__ __forceinline__ ull pack2(float x, float y) {
    ull u; asm("mov.b64 %0, {%1, %2};" : "=l"(u) : "f"(x), "f"(y)); return u;
}
__device__ __forceinline__ float2 u2f(ull u) {
    float2 v; asm("mov.b64 {%0, %1}, %2;" : "=f"(v.x), "=f"(v.y) : "l"(u)); return v;
}
__device__ __forceinline__ ull ffma2(ull a, ull b, ull c) {
    ull d; asm("fma.rn.f32x2 %0, %1, %2, %3;" : "=l"(d) : "l"(a), "l"(b), "l"(c)); return d;
}
__device__ __forceinline__ float tanh_fast(float x) {
    float e = __expf(2.f * x);
    return 1.f - 2.f / (e + 1.f);
}
__device__ __forceinline__ void cp16(void* smem_dst, const void* gsrc) {
    unsigned s = (unsigned)__cvta_generic_to_shared(smem_dst);
    asm volatile("cp.async.ca.shared.global [%0], [%1], 16;\n" :: "r"(s), "l"(gsrc));
}

// ---------------- fused prep kernel: kA (blocks 0..999), kB (1000..1999), kW (2000..2032) ----
__global__ void __launch_bounds__(128) kPrep(
    const float* __restrict__ qew, const float* __restrict__ key_mem,
    const float* __restrict__ sw, const float* __restrict__ sb,
    const float* __restrict__ aw, const float* __restrict__ ab,
    const float* __restrict__ bw, const float* __restrict__ bb,
    const float* __restrict__ iew, const float* __restrict__ vpw,
    const float* __restrict__ vpb, const float* __restrict__ ew,
    const float* __restrict__ eb, const float* __restrict__ aw2,
    const float* __restrict__ ab2, const float* __restrict__ tw) {
    int bid = blockIdx.x;
    if (bid < QQ) {
        int q = bid;
        int t = threadIdx.x;
        __shared__ float qe[64];
        __shared__ float sl[64];
        if (t < 64) qe[t] = qew[q * DK + t];
        __syncthreads();
        float lg = -1e30f;
        if (t < MM) {
            const float* kr = key_mem + t * DK;
            float s = 0.f;
            #pragma unroll
            for (int k = 0; k < DK; k++) s += qe[k] * kr[k];
            lg = s;
        }
        if (t < 64) sl[t] = lg;
        __syncthreads();
        float mx = -1e30f;
        for (int i = 0; i < MM; i++) mx = fmaxf(mx, sl[i]);
        float e = (t < MM) ? expf(sl[t] - mx) : 0.f;
        __syncthreads();
        if (t < 64) sl[t] = e;
        __syncthreads();
        float sm = 0.f;
        for (int i = 0; i < MM; i++) sm += sl[i];
        if (t < 52) g_attn[q * 52 + t] = (t < MM) ? (e / sm) : 0.f;

        float qs = 0.f;
        if (t < 50) {
            float s = sb[t];
            #pragma unroll
            for (int k = 0; k < DK; k++) s += qe[k] * sw[(128 + k) * 50 + t];
            qs = s;
        }
        if (t < 64) g_qsum[q * 64 + t] = qs;

        if (t == 0) {
            float s = ab[0];
            #pragma unroll
            for (int k = 0; k < DK; k++) s += qe[k] * aw[k];
            g_alpha[q] = (s > 20.f) ? s : log1pf(expf(s));
        }
        if (t < 4) {
            float s = bb[t];
            #pragma unroll
            for (int k = 0; k < DK; k++) s += qe[k] * bw[k * 4 + t];
            g_beta[q * 4 + t] = s;
        }
    } else if (bid < 2 * QQ) {
        int q = bid - QQ;
        int v = threadIdx.x;
        __shared__ float iv[64];
        __shared__ float ve_sh[128][8];
        if (v < 64) iv[v] = iew[q * DK + v];
        __syncthreads();
        float base = vpb[v];
        #pragma unroll
        for (int k = 0; k < 64; k++) base += iv[k] * vpw[k * 128 + v];
        float col[5];
        #pragma unroll
        for (int c = 0; c < 5; c++) col[c] = vpw[(64 + c) * 128 + v];
        #pragma unroll
        for (int r = 0; r < 5; r++) {
            float s = base;
            #pragma unroll
            for (int c = 0; c < 5; c++) {
                float rf = fmaxf(0.f, 1.f - fabsf((float)(c - r)) * 0.25f);
                s += rf * col[c];
            }
            ve_sh[v][r] = s;
        }
        __syncthreads();
        float ebv = eb[v], abv = ab2[v];
        ull se01 = pack2(ebv, ebv), se23 = pack2(ebv, ebv); float se4 = ebv;
        ull sa01 = pack2(abv, abv), sa23 = pack2(abv, abv); float sa4 = abv;
        #pragma unroll 4
        for (int i = 0; i < 128; i++) {
            float we = ew[i * 128 + v];
            float wa = aw2[i * 128 + v];
            ull we2 = pack2(we, we), wa2 = pack2(wa, wa);
            const ull* vr = (const ull*)ve_sh[i];
            ull x01 = vr[0], x23 = vr[1];
            float x4 = ve_sh[i][4];
            se01 = ffma2(x01, we2, se01);
            se23 = ffma2(x23, we2, se23);
            se4  = fmaf(x4, we, se4);
            sa01 = ffma2(x01, wa2, sa01);
            sa23 = ffma2(x23, wa2, sa23);
            sa4  = fmaf(x4, wa, sa4);
        }
        float2 s01 = u2f(se01), s23 = u2f(se23);
        float2 a01 = u2f(sa01), a23 = u2f(sa23);
        float er[5] = {s01.x, s01.y, s23.x, s23.y, se4};
        float ar[5] = {a01.x, a01.y, a23.x, a23.y, sa4};
        #pragma unroll
        for (int r = 0; r < 5; r++) {
            float e = 1.f / (1.f + expf(-er[r]));
            float a = tanhf(ar[r]);
            g_ea[(q * 5 + r) * 128 + v] = make_float4(-e, -e, a, a);
        }
    } else {
        int idx = (bid - 2 * QQ) * 128 + threadIdx.x;
        if (idx < DV * 32) {
            int v = idx >> 5, jp = idx & 31;
            int j0 = 2 * jp, j1 = 2 * jp + 1;
            float w0 = (j0 < 50) ? sw[v * 50 + j0] : 0.f;
            float w1 = (j1 < 50) ? sw[v * 50 + j1] : 0.f;
            ((float2*)g_wt2)[idx] = make_float2(w0, w1);
        } else if (idx < DV * 32 + 64) {
            int j = idx - DV * 32;
            g_thw[j] = (j < 50) ? tw[j] : 0.f;
        }
    }
}

// ---------------- scan kernel: 2 CTAs per batch (m-halves), 13 pairs/thread ----------------
// blockIdx.x = b*2 + h? Use: b = bx >> 1, h = bx & 1.
__global__ void __launch_bounds__(128) kScan(const float* __restrict__ init_mem,
                                             const int* __restrict__ questions,
                                             const int* __restrict__ responses) {
    __shared__ int2 s_off[SS];                            // 16KB
    __shared__ alignas(16) float s_attn[2][SG][52];       // 13.3KB double buffer
    int bx = blockIdx.x;
    int b = bx >> 1, h = bx & 1;
    int v = threadIdx.x;

    // per-step offsets
    const int* qp = questions + b * SS;
    const int* rp = responses + b * SS;
    for (int i = v; i < SS; i += 128) {
        int q = qp[i], r = rp[i];
        s_off[i] = make_int2(q * 52, (q * 5 + r) * 128);
    }
    __syncthreads();   // s_off visible to all

    // mem state: 13 f32x2 pairs (global pair gp = h*13+p -> m = 2gp, 2gp+1)
    // h=1, p=12 -> m=50,51: zero init, attn cols 50,51 are 0 -> contributes 0.
    ull mem2[13];
    #pragma unroll
    for (int p = 0; p < 13; p++) {
        int gp = h * 13 + p;
        int m0 = 2 * gp, m1 = 2 * gp + 1;
        float x0 = (m0 < MM) ? init_mem[m0 * DV + v] : 0.f;
        float x1 = (m1 < MM) ? init_mem[m1 * DV + v] : 0.f;
        mem2[p] = pack2(x0, x1);
    }

    // staging map (loop-invariant): 416 float4 slots over 128 threads
    int u_e[4], c4_e[4];
    bool en_e[4];
    #pragma unroll
    for (int e = 0; e < 4; e++) {
        int idx = v + e * 128;
        en_e[e] = (idx < SG * 13);
        u_e[e] = idx / 13;
        c4_e[e] = (idx % 13) * 4;
    }

    // prologue: stage group 0 into buf 0
    #pragma unroll
    for (int e = 0; e < 4; e++)
        if (en_e[e])
            cp16(&s_attn[0][u_e[e]][c4_e[e]], g_attn + s_off[u_e[e]].x + c4_e[e]);
    asm volatile("cp.async.commit_group;");

    // ea register ring, distance 4
    float4 ear[4];
    #pragma unroll
    for (int u = 0; u < 4; u++) ear[u] = __ldg(&g_ea[s_off[u].y + v]);

    float* outp = g_readp + ((size_t)h * BB + b) * SS * DV + v;
    const int aoff = h * 13;
    int buf = 0;

    #pragma unroll 1
    for (int g0 = 0; g0 < SS; g0 += SG) {
        asm volatile("cp.async.wait_group 0;");   // group g0 staged
        __syncthreads();                          // visible to all; prev reads of buf^1 done

        // issue staging for next group into buf^1
        int gn = g0 + SG;
        #pragma unroll
        for (int e = 0; e < 4; e++) {
            if (en_e[e]) {
                int st = gn + u_e[e]; if (st > SS - 1) st = SS - 1;
                cp16(&s_attn[buf ^ 1][u_e[e]][c4_e[e]], g_attn + s_off[st].x + c4_e[e]);
            }
        }
        asm volatile("cp.async.commit_group;");

        // compute 32 steps from buf
        #pragma unroll 4
        for (int u = 0; u < SG; u++) {
            int s = g0 + u;
            float4 ec = ear[s & 3];
            int fs = s + 4; if (fs > SS - 1) fs = SS - 1;
            float4 ean = __ldg(&g_ea[s_off[fs].y + v]);

            ull e2 = pack2(ec.x, ec.y);          // (-e,-e)
            ull d2 = pack2(ec.z, ec.w);          // (a,a)
            ull r0 = 0ull, r1 = 0ull;
            const ull* ap = (const ull*)s_attn[buf][u] + aoff;
            #pragma unroll
            for (int i = 0; i < 13; i++) {
                ull ai = ap[i];                  // LDS.64 broadcast
                if (i & 1) r1 = ffma2(ai, mem2[i], r1);
                else       r0 = ffma2(ai, mem2[i], r0);
                ull t = ffma2(e2, mem2[i], d2);  // add - erase*mem
                mem2[i] = ffma2(ai, t, mem2[i]); // mem += attn*t
            }
            ear[s & 3] = ean;
            float2 f0 = u2f(r0), f1 = u2f(r1);
            __stcs(outp + (size_t)s * DV, (f0.x + f1.x) + (f0.y + f1.y));
        }
        buf ^= 1;
    }
    asm volatile("cp.async.wait_group 0;");
}

// ---------------- epilogue kernel (R2 structure + dual-partial read) ----------------
#define NPOS (BB * SS)
#define OFF_THETA  0
#define OFF_ALPHA  (NPOS)
#define OFF_BETA   (2 * NPOS)
#define OFF_LOGITS (6 * NPOS)
#define OFF_PROBS  (11 * NPOS)

__global__ void __launch_bounds__(128) kEpi(const int* __restrict__ questions,
                                            const float* __restrict__ theta_b,
                                            float* __restrict__ out) {
    int tid = threadIdx.x;
    int pt = tid >> 3;        // 0..15, 4 positions each
    int jt = tid & 7;         // 0..7, 4 j-pairs each
    int pos0 = blockIdx.x * 64 + pt * 4;

    ull acc[4][4];
    #pragma unroll
    for (int k = 0; k < 4; k++)
        #pragma unroll
        for (int c = 0; c < 4; c++) acc[k][c] = 0ull;

    const float4* rpa[4];
    const float4* rpb[4];
    #pragma unroll
    for (int k = 0; k < 4; k++) {
        rpa[k] = (const float4*)(g_readp + (size_t)(pos0 + k) * DV);
        rpb[k] = (const float4*)(g_readp + (size_t)(BB * SS + pos0 + k) * DV);
    }

    #pragma unroll 4
    for (int v4 = 0; v4 < 32; v4++) {
        float4 rd[4];
        #pragma unroll
        for (int k = 0; k < 4; k++) {
            float4 a = __ldg(rpa[k] + v4);
            float4 bq = __ldg(rpb[k] + v4);
            rd[k] = make_float4(a.x + bq.x, a.y + bq.y, a.z + bq.z, a.w + bq.w);
        }
        #pragma unroll
        for (int d = 0; d < 4; d++) {
            int v = v4 * 4 + d;
            const ulonglong2* wr = (const ulonglong2*)(g_wt2 + v * 32 + jt * 4);
            ulonglong2 wA = __ldg(wr);
            ulonglong2 wB = __ldg(wr + 1);
            #pragma unroll
            for (int k = 0; k < 4; k++) {
                float rv = ((const float*)&rd[k])[d];
                ull rvv = pack2(rv, rv);
                acc[k][0] = ffma2(rvv, wA.x, acc[k][0]);
                acc[k][1] = ffma2(rvv, wA.y, acc[k][1]);
                acc[k][2] = ffma2(rvv, wB.x, acc[k][2]);
                acc[k][3] = ffma2(rvv, wB.y, acc[k][3]);
            }
        }
    }

    float tb = __ldg(theta_b);
    #pragma unroll
    for (int k = 0; k < 4; k++) {
        int pos = pos0 + k;
        int q = __ldg(questions + pos);
        const ull* qs2 = ((const ull*)g_qsum) + q * 32 + jt * 4;
        float th = 0.f;
        #pragma unroll
        for (int c = 0; c < 4; c++) {
            float2 s2 = u2f(acc[k][c]);
            float2 qv = u2f(__ldg(qs2 + c));
            int jp = jt * 4 + c;
            float s0 = tanh_fast(s2.x + qv.x);
            float s1 = tanh_fast(s2.y + qv.y);
            th += s0 * g_thw[2 * jp] + s1 * g_thw[2 * jp + 1];
        }
        th += __shfl_xor_sync(0xffffffffu, th, 1);
        th += __shfl_xor_sync(0xffffffffu, th, 2);
        th += __shfl_xor_sync(0xffffffffu, th, 4);
        if (jt == 0) {
            float theta = tanhf(th + tb);
            float alpha = __ldg(g_alpha + q);
            float4 bv = __ldg((const float4*)(g_beta + q * 4));
            float it = theta * alpha;
            float l0 = 0.f;
            float l1 = it - bv.x;
            float l2 = l1 + it - bv.y;
            float l3 = l2 + it - bv.z;
            float l4 = l3 + it - bv.w;
            float m = fmaxf(fmaxf(fmaxf(l0, l1), fmaxf(l2, l3)), l4);
            float e0 = __expf(l0 - m), e1 = __expf(l1 - m), e2 = __expf(l2 - m),
                  e3 = __expf(l3 - m), e4 = __expf(l4 - m);
            float inv = 1.f / (e0 + e1 + e2 + e3 + e4);
            out[OFF_THETA + pos] = theta;
            out[OFF_ALPHA + pos] = alpha;
            ((float4*)(out + OFF_BETA))[pos] = bv;
            float* lo = out + OFF_LOGITS + pos * 5;
            lo[0] = l0; lo[1] = l1; lo[2] = l2; lo[3] = l3; lo[4] = l4;
            float* pr = out + OFF_PROBS + pos * 5;
            pr[0] = e0 * inv; pr[1] = e1 * inv; pr[2] = e2 * inv;
            pr[3] = e3 * inv; pr[4] = e4 * inv;
        }
    }
}

// ---------------- launch ----------------
extern "C" void kernel_launch(void* const* d_in, const int* in_sizes, int n_in,
                              void* d_out, int out_size) {
    const int*   questions    = (const int*)d_in[0];
    const int*   responses    = (const int*)d_in[1];
    const float* q_embed_w    = (const float*)d_in[2];
    const float* item_embed_w = (const float*)d_in[3];
    const float* value_proj_w = (const float*)d_in[4];
    const float* value_proj_b = (const float*)d_in[5];
    const float* key_mem      = (const float*)d_in[6];
    const float* init_mem     = (const float*)d_in[7];
    const float* erase_w      = (const float*)d_in[8];
    const float* erase_b      = (const float*)d_in[9];
    const float* add_w        = (const float*)d_in[10];
    const float* add_b        = (const float*)d_in[11];
    const float* summary_w    = (const float*)d_in[12];
    const float* summary_b    = (const float*)d_in[13];
    const float* theta_w      = (const float*)d_in[14];
    const float* theta_b      = (const float*)d_in[15];
    const float* alpha_w      = (const float*)d_in[16];
    const float* alpha_b      = (const float*)d_in[17];
    const float* beta_w       = (const float*)d_in[18];
    const float* beta_b       = (const float*)d_in[19];
    float* out = (float*)d_out;

    kPrep<<<2 * QQ + 33, 128>>>(q_embed_w, key_mem, summary_w, summary_b,
                                alpha_w, alpha_b, beta_w, beta_b,
                                item_embed_w, value_proj_w, value_proj_b,
                                erase_w, erase_b, add_w, add_b, theta_w);
    kScan<<<2 * BB, 128>>>(init_mem, questions, responses);
    kEpi<<<NPOS / 64, 128>>>(questions, theta_b, out);
}

// round 13
// speedup vs baseline: 1.1006x; 1.1006x over previous
#include <cuda_runtime.h>
#include <cstdint>
#include <math.h>

typedef unsigned long long ull;

#define BB 128
#define SS 2048
#define QQ 1000
#define KK 5
#define MM 50
#define DK 64
#define DV 128
#define SG 32            // scan staging group size

// ---------------- device scratch / tables ----------------
__device__ float g_attn[QQ * 52];          // softmax(q_e @ key^T), row padded to 52 (cols 50,51 = 0)
__device__ float4 g_ea[QQ * KK * DV];      // per (q,r,v): (-erase, -erase, add, add)
__device__ float g_qsum[QQ * 64];          // q_e @ summary_w[128:] + summary_b, j padded to 64
__device__ float g_alpha[QQ];
__device__ float g_beta[QQ * 4];
__device__ ull   g_wt2[DV * 32];           // summary_w[:128] packed float2 over j-pairs
__device__ float g_thw[64];                // theta_w padded to 64 with zeros
__device__ float g_read[BB * SS * DV];     // 134MB read scratch

// ---------------- f32x2 helpers ----------------
__device__ __forceinline__ ull pack2(float x, float y) {
    ull u; asm("mov.b64 %0, {%1, %2};" : "=l"(u) : "f"(x), "f"(y)); return u;
}
__device__ __forceinline__ float2 u2f(ull u) {
    float2 v; asm("mov.b64 {%0, %1}, %2;" : "=f"(v.x), "=f"(v.y) : "l"(u)); return v;
}
__device__ __forceinline__ ull ffma2(ull a, ull b, ull c) {
    ull d; asm("fma.rn.f32x2 %0, %1, %2, %3;" : "=l"(d) : "l"(a), "l"(b), "l"(c)); return d;
}
__device__ __forceinline__ float tanh_fast(float x) {
    float e = __expf(2.f * x);
    return 1.f - 2.f / (e + 1.f);
}
__device__ __forceinline__ void cp16(void* smem_dst, const void* gsrc) {
    unsigned s = (unsigned)__cvta_generic_to_shared(smem_dst);
    asm volatile("cp.async.ca.shared.global [%0], [%1], 16;\n" :: "r"(s), "l"(gsrc));
}

// ---------------- fused prep kernel: kA (blocks 0..999), kB (1000..1999), kW (2000..2032) ----
__global__ void __launch_bounds__(128) kPrep(
    const float* __restrict__ qew, const float* __restrict__ key_mem,
    const float* __restrict__ sw, const float* __restrict__ sb,
    const float* __restrict__ aw, const float* __restrict__ ab,
    const float* __restrict__ bw, const float* __restrict__ bb,
    const float* __restrict__ iew, const float* __restrict__ vpw,
    const float* __restrict__ vpb, const float* __restrict__ ew,
    const float* __restrict__ eb, const float* __restrict__ aw2,
    const float* __restrict__ ab2, const float* __restrict__ tw) {
    int bid = blockIdx.x;
    if (bid < QQ) {
        int q = bid;
        int t = threadIdx.x;
        __shared__ float qe[64];
        __shared__ float sl[64];
        if (t < 64) qe[t] = qew[q * DK + t];
        __syncthreads();
        float lg = -1e30f;
        if (t < MM) {
            const float* kr = key_mem + t * DK;
            float s = 0.f;
            #pragma unroll
            for (int k = 0; k < DK; k++) s += qe[k] * kr[k];
            lg = s;
        }
        if (t < 64) sl[t] = lg;
        __syncthreads();
        float mx = -1e30f;
        for (int i = 0; i < MM; i++) mx = fmaxf(mx, sl[i]);
        float e = (t < MM) ? expf(sl[t] - mx) : 0.f;
        __syncthreads();
        if (t < 64) sl[t] = e;
        __syncthreads();
        float sm = 0.f;
        for (int i = 0; i < MM; i++) sm += sl[i];
        if (t < 52) g_attn[q * 52 + t] = (t < MM) ? (e / sm) : 0.f;

        float qs = 0.f;
        if (t < 50) {
            float s = sb[t];
            #pragma unroll
            for (int k = 0; k < DK; k++) s += qe[k] * sw[(128 + k) * 50 + t];
            qs = s;
        }
        if (t < 64) g_qsum[q * 64 + t] = qs;

        if (t == 0) {
            float s = ab[0];
            #pragma unroll
            for (int k = 0; k < DK; k++) s += qe[k] * aw[k];
            g_alpha[q] = (s > 20.f) ? s : log1pf(expf(s));
        }
        if (t < 4) {
            float s = bb[t];
            #pragma unroll
            for (int k = 0; k < DK; k++) s += qe[k] * bw[k * 4 + t];
            g_beta[q * 4 + t] = s;
        }
    } else if (bid < 2 * QQ) {
        int q = bid - QQ;
        int v = threadIdx.x;
        __shared__ float iv[64];
        __shared__ float ve_sh[128][8];
        if (v < 64) iv[v] = iew[q * DK + v];
        __syncthreads();
        float base = vpb[v];
        #pragma unroll
        for (int k = 0; k < 64; k++) base += iv[k] * vpw[k * 128 + v];
        float col[5];
        #pragma unroll
        for (int c = 0; c < 5; c++) col[c] = vpw[(64 + c) * 128 + v];
        #pragma unroll
        for (int r = 0; r < 5; r++) {
            float s = base;
            #pragma unroll
            for (int c = 0; c < 5; c++) {
                float rf = fmaxf(0.f, 1.f - fabsf((float)(c - r)) * 0.25f);
                s += rf * col[c];
            }
            ve_sh[v][r] = s;
        }
        __syncthreads();
        float ebv = eb[v], abv = ab2[v];
        ull se01 = pack2(ebv, ebv), se23 = pack2(ebv, ebv); float se4 = ebv;
        ull sa01 = pack2(abv, abv), sa23 = pack2(abv, abv); float sa4 = abv;
        #pragma unroll 4
        for (int i = 0; i < 128; i++) {
            float we = ew[i * 128 + v];
            float wa = aw2[i * 128 + v];
            ull we2 = pack2(we, we), wa2 = pack2(wa, wa);
            const ull* vr = (const ull*)ve_sh[i];
            ull x01 = vr[0], x23 = vr[1];
            float x4 = ve_sh[i][4];
            se01 = ffma2(x01, we2, se01);
            se23 = ffma2(x23, we2, se23);
            se4  = fmaf(x4, we, se4);
            sa01 = ffma2(x01, wa2, sa01);
            sa23 = ffma2(x23, wa2, sa23);
            sa4  = fmaf(x4, wa, sa4);
        }
        float2 s01 = u2f(se01), s23 = u2f(se23);
        float2 a01 = u2f(sa01), a23 = u2f(sa23);
        float er[5] = {s01.x, s01.y, s23.x, s23.y, se4};
        float ar[5] = {a01.x, a01.y, a23.x, a23.y, sa4};
        #pragma unroll
        for (int r = 0; r < 5; r++) {
            float e = 1.f / (1.f + expf(-er[r]));
            float a = tanhf(ar[r]);
            g_ea[(q * 5 + r) * 128 + v] = make_float4(-e, -e, a, a);
        }
    } else {
        int idx = (bid - 2 * QQ) * 128 + threadIdx.x;
        if (idx < DV * 32) {
            int v = idx >> 5, jp = idx & 31;
            int j0 = 2 * jp, j1 = 2 * jp + 1;
            float w0 = (j0 < 50) ? sw[v * 50 + j0] : 0.f;
            float w1 = (j1 < 50) ? sw[v * 50 + j1] : 0.f;
            ((float2*)g_wt2)[idx] = make_float2(w0, w1);
        } else if (idx < DV * 32 + 64) {
            int j = idx - DV * 32;
            g_thw[j] = (j < 50) ? tw[j] : 0.f;
        }
    }
}

// ---------------- scan kernel: R10 exact (128 threads, LDS.128, 32-step staging) ----
__global__ void __launch_bounds__(128) kScan(const float* __restrict__ init_mem,
                                             const int* __restrict__ questions,
                                             const int* __restrict__ responses) {
    __shared__ int2 s_off[SS];                            // 16KB
    __shared__ alignas(16) float s_attn[2][SG][52];       // 13.3KB double buffer
    int b = blockIdx.x, v = threadIdx.x;

    // per-step offsets
    const int* qp = questions + b * SS;
    const int* rp = responses + b * SS;
    for (int i = v; i < SS; i += 128) {
        int q = qp[i], r = rp[i];
        s_off[i] = make_int2(q * 52, (q * 5 + r) * 128);
    }
    __syncthreads();   // s_off visible to all

    // mem state: 26 f32x2 pairs over m (pair 25 = zero padding; attn cols 50,51 = 0)
    ull mem2[26];
    #pragma unroll
    for (int i = 0; i < 25; i++)
        mem2[i] = pack2(init_mem[(2 * i) * DV + v], init_mem[(2 * i + 1) * DV + v]);
    mem2[25] = 0ull;

    // staging map (loop-invariant): 416 float4 slots over 128 threads
    int u_e[4], c4_e[4];
    bool en_e[4];
    #pragma unroll
    for (int e = 0; e < 4; e++) {
        int idx = v + e * 128;
        en_e[e] = (idx < SG * 13);
        u_e[e] = idx / 13;
        c4_e[e] = (idx % 13) * 4;
    }

    // prologue: stage group 0 into buf 0
    #pragma unroll
    for (int e = 0; e < 4; e++)
        if (en_e[e])
            cp16(&s_attn[0][u_e[e]][c4_e[e]], g_attn + s_off[u_e[e]].x + c4_e[e]);
    asm volatile("cp.async.commit_group;");

    // ea register ring, distance 4
    float4 ear[4];
    #pragma unroll
    for (int u = 0; u < 4; u++) ear[u] = __ldg(&g_ea[s_off[u].y + v]);

    float* outp = g_read + (size_t)b * SS * DV + v;
    int buf = 0;

    #pragma unroll 1
    for (int g0 = 0; g0 < SS; g0 += SG) {
        asm volatile("cp.async.wait_group 0;");   // group g0 staged
        __syncthreads();                          // visible to all; prev reads of buf^1 done

        // issue staging for next group into buf^1
        int gn = g0 + SG;
        #pragma unroll
        for (int e = 0; e < 4; e++) {
            if (en_e[e]) {
                int st = gn + u_e[e]; if (st > SS - 1) st = SS - 1;
                cp16(&s_attn[buf ^ 1][u_e[e]][c4_e[e]], g_attn + s_off[st].x + c4_e[e]);
            }
        }
        asm volatile("cp.async.commit_group;");

        // compute 32 steps from buf
        #pragma unroll 4
        for (int u = 0; u < SG; u++) {
            int s = g0 + u;
            float4 ec = ear[s & 3];
            int fs = s + 4; if (fs > SS - 1) fs = SS - 1;
            float4 ean = __ldg(&g_ea[s_off[fs].y + v]);

            ull e2 = pack2(ec.x, ec.y);          // (-e,-e)
            ull d2 = pack2(ec.z, ec.w);          // (a,a)
            ull r0 = 0ull, r1 = 0ull;
            const ulonglong2* ap2 = (const ulonglong2*)s_attn[buf][u];
            #pragma unroll
            for (int i = 0; i < 13; i++) {
                ulonglong2 a2 = ap2[i];          // LDS.128 broadcast
                ull m0 = mem2[2 * i], m1 = mem2[2 * i + 1];
                r0 = ffma2(a2.x, m0, r0);
                r1 = ffma2(a2.y, m1, r1);
                ull t0 = ffma2(e2, m0, d2);      // add - erase*mem
                ull t1 = ffma2(e2, m1, d2);
                mem2[2 * i]     = ffma2(a2.x, t0, m0);
                mem2[2 * i + 1] = ffma2(a2.y, t1, m1);
            }
            ear[s & 3] = ean;
            float2 f0 = u2f(r0), f1 = u2f(r1);
            __stcs(outp + (size_t)s * DV, (f0.x + f1.x) + (f0.y + f1.y));
        }
        buf ^= 1;
    }
    asm volatile("cp.async.wait_group 0;");
}

// ---------------- epilogue kernel: R2 structure + smem-staged weights ----------------
#define NPOS (BB * SS)
#define OFF_THETA  0
#define OFF_ALPHA  (NPOS)
#define OFF_BETA   (2 * NPOS)
#define OFF_LOGITS (6 * NPOS)
#define OFF_PROBS  (11 * NPOS)

__global__ void __launch_bounds__(128) kEpi(const int* __restrict__ questions,
                                            const float* __restrict__ theta_b,
                                            float* __restrict__ out) {
    __shared__ alignas(16) ull s_wt[DV * 32];   // 32KB packed weight table
    int tid = threadIdx.x;
    int pt = tid >> 3;        // 0..15, 4 positions each
    int jt = tid & 7;         // 0..7, 4 j-pairs each
    int pos0 = blockIdx.x * 64 + pt * 4;

    // stage weights: 2048 float4 over 128 threads (16 each)
    #pragma unroll
    for (int e = 0; e < 16; e++) {
        int idx = tid + e * 128;
        cp16(((float4*)s_wt) + idx, ((const float4*)g_wt2) + idx);
    }
    asm volatile("cp.async.commit_group;");
    asm volatile("cp.async.wait_group 0;");
    __syncthreads();

    ull acc[4][4];
    #pragma unroll
    for (int k = 0; k < 4; k++)
        #pragma unroll
        for (int c = 0; c < 4; c++) acc[k][c] = 0ull;

    const float4* rp0 = (const float4*)(g_read + (size_t)(pos0 + 0) * DV);
    const float4* rp1 = (const float4*)(g_read + (size_t)(pos0 + 1) * DV);
    const float4* rp2 = (const float4*)(g_read + (size_t)(pos0 + 2) * DV);
    const float4* rp3 = (const float4*)(g_read + (size_t)(pos0 + 3) * DV);

    #pragma unroll 4
    for (int v4 = 0; v4 < 32; v4++) {
        float4 rd[4];
        rd[0] = __ldg(rp0 + v4);
        rd[1] = __ldg(rp1 + v4);
        rd[2] = __ldg(rp2 + v4);
        rd[3] = __ldg(rp3 + v4);
        #pragma unroll
        for (int d = 0; d < 4; d++) {
            int v = v4 * 4 + d;
            const ulonglong2* wr = (const ulonglong2*)(s_wt + v * 32 + jt * 4);
            ulonglong2 wA = wr[0];               // LDS.128
            ulonglong2 wB = wr[1];               // LDS.128
            #pragma unroll
            for (int k = 0; k < 4; k++) {
                float rv = ((const float*)&rd[k])[d];
                ull rvv = pack2(rv, rv);
                acc[k][0] = ffma2(rvv, wA.x, acc[k][0]);
                acc[k][1] = ffma2(rvv, wA.y, acc[k][1]);
                acc[k][2] = ffma2(rvv, wB.x, acc[k][2]);
                acc[k][3] = ffma2(rvv, wB.y, acc[k][3]);
            }
        }
    }

    float tb = __ldg(theta_b);
    #pragma unroll
    for (int k = 0; k < 4; k++) {
        int pos = pos0 + k;
        int q = __ldg(questions + pos);
        const ull* qs2 = ((const ull*)g_qsum) + q * 32 + jt * 4;
        float th = 0.f;
        #pragma unroll
        for (int c = 0; c < 4; c++) {
            float2 s2 = u2f(acc[k][c]);
            float2 qv = u2f(__ldg(qs2 + c));
            int jp = jt * 4 + c;
            float s0 = tanh_fast(s2.x + qv.x);
            float s1 = tanh_fast(s2.y + qv.y);
            th += s0 * g_thw[2 * jp] + s1 * g_thw[2 * jp + 1];
        }
        th += __shfl_xor_sync(0xffffffffu, th, 1);
        th += __shfl_xor_sync(0xffffffffu, th, 2);
        th += __shfl_xor_sync(0xffffffffu, th, 4);
        if (jt == 0) {
            float theta = tanhf(th + tb);
            float alpha = __ldg(g_alpha + q);
            float4 bv = __ldg((const float4*)(g_beta + q * 4));
            float it = theta * alpha;
            float l0 = 0.f;
            float l1 = it - bv.x;
            float l2 = l1 + it - bv.y;
            float l3 = l2 + it - bv.z;
            float l4 = l3 + it - bv.w;
            float m = fmaxf(fmaxf(fmaxf(l0, l1), fmaxf(l2, l3)), l4);
            float e0 = __expf(l0 - m), e1 = __expf(l1 - m), e2 = __expf(l2 - m),
                  e3 = __expf(l3 - m), e4 = __expf(l4 - m);
            float inv = 1.f / (e0 + e1 + e2 + e3 + e4);
            out[OFF_THETA + pos] = theta;
            out[OFF_ALPHA + pos] = alpha;
            ((float4*)(out + OFF_BETA))[pos] = bv;
            float* lo = out + OFF_LOGITS + pos * 5;
            lo[0] = l0; lo[1] = l1; lo[2] = l2; lo[3] = l3; lo[4] = l4;
            float* pr = out + OFF_PROBS + pos * 5;
            pr[0] = e0 * inv; pr[1] = e1 * inv; pr[2] = e2 * inv;
            pr[3] = e3 * inv; pr[4] = e4 * inv;
        }
    }
}

// ---------------- launch ----------------
extern "C" void kernel_launch(void* const* d_in, const int* in_sizes, int n_in,
                              void* d_out, int out_size) {
    const int*   questions    = (const int*)d_in[0];
    const int*   responses    = (const int*)d_in[1];
    const float* q_embed_w    = (const float*)d_in[2];
    const float* item_embed_w = (const float*)d_in[3];
    const float* value_proj_w = (const float*)d_in[4];
    const float* value_proj_b = (const float*)d_in[5];
    const float* key_mem      = (const float*)d_in[6];
    const float* init_mem     = (const float*)d_in[7];
    const float* erase_w      = (const float*)d_in[8];
    const float* erase_b      = (const float*)d_in[9];
    const float* add_w        = (const float*)d_in[10];
    const float* add_b        = (const float*)d_in[11];
    const float* summary_w    = (const float*)d_in[12];
    const float* summary_b    = (const float*)d_in[13];
    const float* theta_w      = (const float*)d_in[14];
    const float* theta_b      = (const float*)d_in[15];
    const float* alpha_w      = (const float*)d_in[16];
    const float* alpha_b      = (const float*)d_in[17];
    const float* beta_w       = (const float*)d_in[18];
    const float* beta_b       = (const float*)d_in[19];
    float* out = (float*)d_out;

    kPrep<<<2 * QQ + 33, 128>>>(q_embed_w, key_mem, summary_w, summary_b,
                                alpha_w, alpha_b, beta_w, beta_b,
                                item_embed_w, value_proj_w, value_proj_b,
                                erase_w, erase_b, add_w, add_b, theta_w);
    kScan<<<BB, 128>>>(init_mem, questions, responses);
    kEpi<<<NPOS / 64, 128>>>(questions, theta_b, out);
}